// round 1
// baseline (speedup 1.0000x reference)
#include <cuda_runtime.h>
#include <math.h>

#define ECNT   300000
#define IECNT  300000
#define NENT   100000
#define NUSR   50000
#define DD     256
#define NRELM1 20
#define EPSV   1e-8f
#define GAMMAV 0.2f

// ---------------- scratch (device globals; no allocations allowed) -----------
__device__ float g_seg_omega[NENT];
__device__ float g_seg_eta[NENT];
__device__ float g_cnt[NENT];
__device__ float g_alpha[ECNT];
__device__ float g_eta[ECNT];           // holds eta0 then eta
__device__ float g_ent[2][NENT * DD];   // ping-pong entity buffers (~205 MB)
__device__ float g_usr[NUSR * DD];      // user scatter accumulator

// ---------------- helpers ----------------------------------------------------
__device__ __forceinline__ float blockReduceSum256(float v) {
    __shared__ float s[8];
    int tid = threadIdx.x;
    int lane = tid & 31, wid = tid >> 5;
    #pragma unroll
    for (int o = 16; o > 0; o >>= 1) v += __shfl_down_sync(0xffffffffu, v, o);
    if (lane == 0) s[wid] = v;
    __syncthreads();
    if (tid == 0) {
        float t = 0.f;
        #pragma unroll
        for (int i = 0; i < 8; i++) t += s[i];
        s[0] = t;
    }
    __syncthreads();
    return s[0];
}

__device__ __forceinline__ float cleanv(float v) {
    if (isnan(v)) return 0.0f;
    if (isinf(v)) return v > 0.f ? 10000.0f : 0.0001f;
    return v;
}

// ---------------- precompute (alpha / eta / cnt) ------------------------------
__global__ void k_zero_seg() {
    int i = blockIdx.x * blockDim.x + threadIdx.x;
    if (i < NENT) { g_seg_omega[i] = 0.f; g_seg_eta[i] = 0.f; g_cnt[i] = 0.f; }
}

__global__ void k_seg_omega(const int* __restrict__ head, const float* __restrict__ omega) {
    int e = blockIdx.x * blockDim.x + threadIdx.x;
    if (e < ECNT) {
        int h = head[e];
        atomicAdd(&g_seg_omega[h], omega[e]);
        atomicAdd(&g_cnt[h], 1.0f);
    }
}

__global__ void k_alpha_eta0(const int* __restrict__ head, const float* __restrict__ omega) {
    int e = blockIdx.x * blockDim.x + threadIdx.x;
    if (e < ECNT) {
        int h = head[e];
        float a = omega[e] / (g_seg_omega[h] + EPSV);
        g_alpha[e] = a;
        float e0 = (a > GAMMAV) ? a : 0.0f;
        g_eta[e] = e0;
        atomicAdd(&g_seg_eta[h], e0);
    }
}

__global__ void k_eta(const int* __restrict__ head) {
    int e = blockIdx.x * blockDim.x + threadIdx.x;
    if (e < ECNT) {
        g_eta[e] = g_eta[e] / (g_seg_eta[head[e]] + EPSV);
    }
}

// ---------------- init: residuals + entity state ------------------------------
__global__ void k_init(const float* __restrict__ user_emb,
                       const float* __restrict__ entity_emb,
                       float* __restrict__ out) {
    long i = (long)blockIdx.x * blockDim.x + threadIdx.x;
    long stride = (long)gridDim.x * blockDim.x;
    const long NE = (long)NENT * DD, NU = (long)NUSR * DD;
    for (long k = i; k < NE; k += stride) {
        float v = entity_emb[k];
        g_ent[0][k] = v;
        out[k] = v;
    }
    for (long k = i; k < NU; k += stride) {
        out[NE + k] = user_emb[k];
    }
}

// ---------------- per-hop zero of scatter targets -----------------------------
__global__ void k_zero_hop(int dst) {
    long i = (long)blockIdx.x * blockDim.x + threadIdx.x;
    long stride = (long)gridDim.x * blockDim.x;
    const long NE = (long)NENT * DD, NU = (long)NUSR * DD;
    for (long k = i; k < NE; k += stride) g_ent[dst][k] = 0.f;
    for (long k = i; k < NU; k += stride) g_usr[k] = 0.f;
}

// ---------------- KG scatter: one block (256 thr) per edge --------------------
__global__ void k_kg_scatter(int src, int useEta,
                             const int* __restrict__ head,
                             const int* __restrict__ tail,
                             const int* __restrict__ etype,
                             const float* __restrict__ rel) {
    int e = blockIdx.x;
    int c = threadIdx.x;
    float rho = useEta ? g_eta[e] : g_alpha[e];
    int h = head[e];
    int t = tail[e];
    int ty = etype[e] - 1;
    float v = rho * g_ent[src][(long)t * DD + c] * rel[(long)ty * DD + c];
    atomicAdd(&g_ent[src ^ 1][(long)h * DD + c], v);
}

// ---------------- interaction scatter: one block per inter edge ---------------
__global__ void k_inter_scatter(int src,
                                const int* __restrict__ iu,
                                const int* __restrict__ ii,
                                const float* __restrict__ w) {
    int e = blockIdx.x;
    int c = threadIdx.x;
    int u = iu[e];
    int it = ii[e];
    float v = w[e] * g_ent[src][(long)it * DD + c];
    atomicAdd(&g_usr[(long)u * DD + c], v);
}

// ---------------- entity normalize: mean -> l2norm -> clean -> accumulate -----
__global__ void k_ent_norm(int buf, float* __restrict__ out) {
    int row = blockIdx.x;
    int c = threadIdx.x;
    long idx = (long)row * DD + c;
    float cnt = fmaxf(g_cnt[row], 1.0f);
    float x = g_ent[buf][idx] / cnt;
    float ss = blockReduceSum256(x * x);
    float n = sqrtf(ss);
    float v = cleanv(x / fmaxf(n, EPSV));
    g_ent[buf][idx] = v;      // becomes input state for next hop
    out[idx] += v;            // residual accumulation
}

// ---------------- user normalize ----------------------------------------------
__global__ void k_usr_norm(float* __restrict__ out) {
    int row = blockIdx.x;
    int c = threadIdx.x;
    long idx = (long)row * DD + c;
    float x = g_usr[idx];
    float ss = blockReduceSum256(x * x);
    float n = sqrtf(ss);
    float v = cleanv(x / fmaxf(n, EPSV));
    out[(long)NENT * DD + idx] += v;
}

// ---------------- launch ------------------------------------------------------
extern "C" void kernel_launch(void* const* d_in, const int* in_sizes, int n_in,
                              void* d_out, int out_size) {
    const float* user_emb    = (const float*)d_in[0];
    const float* entity_emb  = (const float*)d_in[1];
    const int*   edge_index  = (const int*)d_in[2];   // [2, E]
    const int*   edge_type   = (const int*)d_in[3];
    const float* omega       = (const float*)d_in[4];
    const int*   inter_edge  = (const int*)d_in[5];   // [2, IE]
    const float* inter_w     = (const float*)d_in[6];
    const float* rel_emb     = (const float*)d_in[7];
    float* out = (float*)d_out;

    const int* head = edge_index;
    const int* tail = edge_index + ECNT;
    const int* iu   = inter_edge;
    const int* ii   = inter_edge + IECNT;

    const int T = 256;
    // precompute alpha / eta / cnt
    k_zero_seg<<<(NENT + T - 1) / T, T>>>();
    k_seg_omega<<<(ECNT + T - 1) / T, T>>>(head, omega);
    k_alpha_eta0<<<(ECNT + T - 1) / T, T>>>(head, omega);
    k_eta<<<(ECNT + T - 1) / T, T>>>(head);

    // residual init + entity state
    k_init<<<2048, T>>>(user_emb, entity_emb, out);

    int src = 0;
    for (int hop = 0; hop < 3; hop++) {
        int dst = src ^ 1;
        int useEta = (hop == 2) ? 1 : 0;
        k_zero_hop<<<2048, T>>>(dst);
        k_kg_scatter<<<ECNT, T>>>(src, useEta, head, tail, edge_type, rel_emb);
        k_inter_scatter<<<IECNT, T>>>(src, iu, ii, inter_w);
        k_ent_norm<<<NENT, T>>>(dst, out);
        k_usr_norm<<<NUSR, T>>>(out);
        src = dst;
    }
}

// round 2
// speedup vs baseline: 2.8719x; 2.8719x over previous
#include <cuda_runtime.h>
#include <math.h>

#define ECNT   300000
#define IECNT  300000
#define NENT   100000
#define NUSR   50000
#define DD     256
#define D4     64
#define EPSV   1e-8f
#define GAMMAV 0.2f

// ---------------- scratch (device globals; no allocations allowed) -----------
__device__ int   g_cnt_e[NENT];
__device__ int   g_cnt_u[NUSR];
__device__ int   g_off_e[NENT + 1];
__device__ int   g_off_u[NUSR + 1];
__device__ int   g_cur_e[NENT];
__device__ int   g_cur_u[NUSR];
__device__ float g_seg_omega[NENT];
__device__ float g_seg_eta[NENT];
__device__ float g_alpha[ECNT];   // per-edge alpha (edge order)
__device__ float g_eta0[ECNT];    // per-edge eta0  (edge order)
// CSR-permuted edge payloads
__device__ int   g_p_tail[ECNT];
__device__ int   g_p_rel[ECNT];   // 0-based relation id
__device__ float g_p_alpha[ECNT];
__device__ float g_p_eta[ECNT];
__device__ int   g_p_item[IECNT];
__device__ float g_p_w[IECNT];
// ping-pong entity state (input embedding serves as hop-0 source)
__device__ float g_ent[2][NENT * DD];

// ---------------- helpers ----------------------------------------------------
__device__ __forceinline__ float red64(float v) {
    #pragma unroll
    for (int o = 16; o > 0; o >>= 1) v += __shfl_down_sync(0xffffffffu, v, o);
    __shared__ float s[2];
    int t = threadIdx.x;
    if ((t & 31) == 0) s[t >> 5] = v;
    __syncthreads();
    float r = s[0] + s[1];
    __syncthreads();
    return r;
}

__device__ __forceinline__ float cleanv(float v) {
    if (isnan(v)) return 0.0f;
    if (isinf(v)) return v > 0.f ? 10000.0f : 0.0001f;
    return v;
}

__device__ __forceinline__ const float4* ent_src(int sel, const float4* in) {
    return sel < 0 ? in : (const float4*)g_ent[sel];
}

// ---------------- CSR build ---------------------------------------------------
__global__ void k_zero() {
    int i = blockIdx.x * blockDim.x + threadIdx.x;
    if (i < NENT) { g_cnt_e[i] = 0; g_seg_omega[i] = 0.f; g_seg_eta[i] = 0.f; }
    if (i < NUSR) { g_cnt_u[i] = 0; }
}

__global__ void k_count(const int* __restrict__ head, const float* __restrict__ omega,
                        const int* __restrict__ iu) {
    int e = blockIdx.x * blockDim.x + threadIdx.x;
    if (e < ECNT) {
        int h = head[e];
        atomicAdd(&g_cnt_e[h], 1);
        atomicAdd(&g_seg_omega[h], omega[e]);
    }
    if (e < IECNT) {
        atomicAdd(&g_cnt_u[iu[e]], 1);
    }
}

__global__ void k_alpha(const int* __restrict__ head, const float* __restrict__ omega) {
    int e = blockIdx.x * blockDim.x + threadIdx.x;
    if (e < ECNT) {
        int h = head[e];
        float a = omega[e] / (g_seg_omega[h] + EPSV);
        g_alpha[e] = a;
        float e0 = (a > GAMMAV) ? a : 0.0f;
        g_eta0[e] = e0;
        atomicAdd(&g_seg_eta[h], e0);
    }
}

// single-block exclusive scan (1024 elems per iteration: 256 threads x 4)
__global__ void k_scan(int which) {
    const int n   = which ? NUSR    : NENT;
    const int* cnt = which ? g_cnt_u : g_cnt_e;
    int* off       = which ? g_off_u : g_off_e;
    int* cur       = which ? g_cur_u : g_cur_e;
    __shared__ int sh[256];
    __shared__ int carry_s;
    int t = threadIdx.x;
    if (t == 0) carry_s = 0;
    __syncthreads();
    for (int base = 0; base < n; base += 1024) {
        int v[4], loc = 0;
        #pragma unroll
        for (int k = 0; k < 4; k++) {
            int i = base + t * 4 + k;
            v[k] = (i < n) ? cnt[i] : 0;
            loc += v[k];
        }
        sh[t] = loc;
        __syncthreads();
        #pragma unroll
        for (int o = 1; o < 256; o <<= 1) {
            int x = (t >= o) ? sh[t - o] : 0;
            __syncthreads();
            sh[t] += x;
            __syncthreads();
        }
        int excl = carry_s + ((t > 0) ? sh[t - 1] : 0);
        #pragma unroll
        for (int k = 0; k < 4; k++) {
            int i = base + t * 4 + k;
            if (i < n) { off[i] = excl; cur[i] = excl; }
            excl += v[k];
        }
        __syncthreads();
        if (t == 0) carry_s += sh[255];
        __syncthreads();
    }
    if (t == 0) off[n] = carry_s;
}

__global__ void k_fill(const int* __restrict__ head, const int* __restrict__ tail,
                       const int* __restrict__ etype,
                       const int* __restrict__ iu, const int* __restrict__ ii,
                       const float* __restrict__ w) {
    int e = blockIdx.x * blockDim.x + threadIdx.x;
    if (e < ECNT) {
        int h = head[e];
        int pos = atomicAdd(&g_cur_e[h], 1);
        g_p_tail[pos]  = tail[e];
        g_p_rel[pos]   = etype[e] - 1;
        g_p_alpha[pos] = g_alpha[e];
        g_p_eta[pos]   = g_eta0[e] / (g_seg_eta[h] + EPSV);
    }
    if (e < IECNT) {
        int u = iu[e];
        int pos = atomicAdd(&g_cur_u[u], 1);
        g_p_item[pos] = ii[e];
        g_p_w[pos]    = w[e];
    }
}

// ---------------- fused hop kernels -------------------------------------------
// One 64-thread block per entity row; each thread owns one float4 (4 channels).
// Gathers incoming messages, scatter_mean, l2norm, clean, writes next state and
// accumulates the residual into out — all in one pass, no atomics, no zeroing.
__global__ void k_ent_hop(int srcSel, int dstSel, int useEta, int hop0,
                          const float4* __restrict__ in_ent,
                          const float4* __restrict__ rel4,
                          float4* __restrict__ outE) {
    const float4* src = ent_src(srcSel, in_ent);
    float4* dst = (float4*)g_ent[dstSel];
    int row = blockIdx.x;
    int c   = threadIdx.x;
    int beg = g_off_e[row], end = g_off_e[row + 1];
    float4 acc = make_float4(0.f, 0.f, 0.f, 0.f);
    for (int p = beg; p < end; ++p) {
        int   t   = g_p_tail[p];
        int   r   = g_p_rel[p];
        float rho = useEta ? g_p_eta[p] : g_p_alpha[p];
        float4 ev = src[(long)t * D4 + c];
        float4 rv = rel4[(long)r * D4 + c];
        acc.x = fmaf(rho * rv.x, ev.x, acc.x);
        acc.y = fmaf(rho * rv.y, ev.y, acc.y);
        acc.z = fmaf(rho * rv.z, ev.z, acc.z);
        acc.w = fmaf(rho * rv.w, ev.w, acc.w);
    }
    float inv = 1.0f / fmaxf((float)(end - beg), 1.0f);
    float4 x = make_float4(acc.x * inv, acc.y * inv, acc.z * inv, acc.w * inv);
    float ss = red64(x.x * x.x + x.y * x.y + x.z * x.z + x.w * x.w);
    float innorm = 1.0f / fmaxf(sqrtf(ss), EPSV);
    float4 v = make_float4(cleanv(x.x * innorm), cleanv(x.y * innorm),
                           cleanv(x.z * innorm), cleanv(x.w * innorm));
    long rb = (long)row * D4 + c;
    dst[rb] = v;
    float4 b = hop0 ? src[rb] : outE[rb];
    outE[rb] = make_float4(b.x + v.x, b.y + v.y, b.z + v.z, b.w + v.w);
}

__global__ void k_usr_hop(int srcSel, int hop0,
                          const float4* __restrict__ in_ent,
                          const float4* __restrict__ user4,
                          float4* __restrict__ outU) {
    const float4* src = ent_src(srcSel, in_ent);
    int row = blockIdx.x;
    int c   = threadIdx.x;
    int beg = g_off_u[row], end = g_off_u[row + 1];
    float4 acc = make_float4(0.f, 0.f, 0.f, 0.f);
    for (int p = beg; p < end; ++p) {
        int   it = g_p_item[p];
        float w  = g_p_w[p];
        float4 ev = src[(long)it * D4 + c];
        acc.x = fmaf(w, ev.x, acc.x);
        acc.y = fmaf(w, ev.y, acc.y);
        acc.z = fmaf(w, ev.z, acc.z);
        acc.w = fmaf(w, ev.w, acc.w);
    }
    float ss = red64(acc.x * acc.x + acc.y * acc.y + acc.z * acc.z + acc.w * acc.w);
    float innorm = 1.0f / fmaxf(sqrtf(ss), EPSV);
    float4 v = make_float4(cleanv(acc.x * innorm), cleanv(acc.y * innorm),
                           cleanv(acc.z * innorm), cleanv(acc.w * innorm));
    long rb = (long)row * D4 + c;
    float4 b = hop0 ? user4[rb] : outU[rb];
    outU[rb] = make_float4(b.x + v.x, b.y + v.y, b.z + v.z, b.w + v.w);
}

// ---------------- launch ------------------------------------------------------
extern "C" void kernel_launch(void* const* d_in, const int* in_sizes, int n_in,
                              void* d_out, int out_size) {
    const float* user_emb   = (const float*)d_in[0];
    const float* entity_emb = (const float*)d_in[1];
    const int*   edge_index = (const int*)d_in[2];   // [2, E]
    const int*   edge_type  = (const int*)d_in[3];
    const float* omega      = (const float*)d_in[4];
    const int*   inter_edge = (const int*)d_in[5];   // [2, IE]
    const float* inter_w    = (const float*)d_in[6];
    const float* rel_emb    = (const float*)d_in[7];
    float* out = (float*)d_out;

    const int* head = edge_index;
    const int* tail = edge_index + ECNT;
    const int* iu   = inter_edge;
    const int* ii   = inter_edge + IECNT;

    const float4* ent_in = (const float4*)entity_emb;
    const float4* usr_in = (const float4*)user_emb;
    const float4* rel4   = (const float4*)rel_emb;
    float4* outE = (float4*)out;
    float4* outU = (float4*)(out + (long)NENT * DD);

    const int T = 256;
    // CSR build + alpha/eta precompute
    k_zero <<<(NENT + T - 1) / T, T>>>();
    k_count<<<(ECNT + T - 1) / T, T>>>(head, omega, iu);
    k_alpha<<<(ECNT + T - 1) / T, T>>>(head, omega);
    k_scan <<<1, T>>>(0);
    k_scan <<<1, T>>>(1);
    k_fill <<<(ECNT + T - 1) / T, T>>>(head, tail, edge_type, iu, ii, inter_w);

    // hops: hop0 reads the input embeddings directly (srcSel = -1)
    // hop 1: src=input, dst=buf0 ; hop 2: src=buf0, dst=buf1 ; hop 3: src=buf1, dst=buf0
    k_ent_hop<<<NENT, D4>>>(-1, 0, /*useEta=*/0, /*hop0=*/1, ent_in, rel4, outE);
    k_usr_hop<<<NUSR, D4>>>(-1,    /*hop0=*/1, ent_in, usr_in, outU);

    k_ent_hop<<<NENT, D4>>>(0, 1, /*useEta=*/0, /*hop0=*/0, ent_in, rel4, outE);
    k_usr_hop<<<NUSR, D4>>>(0,    /*hop0=*/0, ent_in, usr_in, outU);

    k_ent_hop<<<NENT, D4>>>(1, 0, /*useEta=*/1, /*hop0=*/0, ent_in, rel4, outE);
    k_usr_hop<<<NUSR, D4>>>(1,    /*hop0=*/0, ent_in, usr_in, outU);
}

// round 3
// speedup vs baseline: 4.3198x; 1.5042x over previous
#include <cuda_runtime.h>
#include <math.h>

#define ECNT   300000
#define IECNT  300000
#define NENT   100000
#define NUSR   50000
#define DD     256
#define D4     64
#define EPSV   1e-8f
#define GAMMAV 0.2f

// ---------------- scratch (device globals; no allocations allowed) -----------
__device__ int   g_cnt_e[NENT];
__device__ int   g_cnt_u[NUSR];
__device__ int   g_off_e[NENT + 1];
__device__ int   g_off_u[NUSR + 1];
__device__ int   g_cur_e[NENT];
__device__ int   g_cur_u[NUSR];
__device__ float g_seg_omega[NENT];
__device__ float g_seg_eta[NENT];
__device__ float g_alpha[ECNT];   // per-edge alpha (edge order)
__device__ float g_eta0[ECNT];    // per-edge eta0  (edge order)
// CSR-permuted edge payloads
__device__ int   g_p_tail[ECNT];
__device__ int   g_p_rel[ECNT];   // 0-based relation id
__device__ float g_p_alpha[ECNT];
__device__ float g_p_eta[ECNT];
__device__ int   g_p_item[IECNT];
__device__ float g_p_w[IECNT];
// ping-pong entity state (input embedding serves as hop-0 source)
__device__ float g_ent[2][NENT * DD];

// ---------------- helpers ----------------------------------------------------
__device__ __forceinline__ float red64(float v) {
    #pragma unroll
    for (int o = 16; o > 0; o >>= 1) v += __shfl_down_sync(0xffffffffu, v, o);
    __shared__ float s[2];
    int t = threadIdx.x;
    if ((t & 31) == 0) s[t >> 5] = v;
    __syncthreads();
    float r = s[0] + s[1];
    __syncthreads();
    return r;
}

__device__ __forceinline__ float cleanv(float v) {
    if (isnan(v)) return 0.0f;
    if (isinf(v)) return v > 0.f ? 10000.0f : 0.0001f;
    return v;
}

// ---------------- CSR build ---------------------------------------------------
__global__ void k_zero() {
    int i = blockIdx.x * blockDim.x + threadIdx.x;
    if (i < NENT) { g_cnt_e[i] = 0; g_seg_omega[i] = 0.f; g_seg_eta[i] = 0.f; }
    if (i < NUSR) { g_cnt_u[i] = 0; }
}

__global__ void k_count(const int* __restrict__ head, const float* __restrict__ omega,
                        const int* __restrict__ iu) {
    int e = blockIdx.x * blockDim.x + threadIdx.x;
    if (e < ECNT) {
        int h = head[e];
        atomicAdd(&g_cnt_e[h], 1);
        atomicAdd(&g_seg_omega[h], omega[e]);
    }
    if (e < IECNT) {
        atomicAdd(&g_cnt_u[iu[e]], 1);
    }
}

__global__ void k_alpha(const int* __restrict__ head, const float* __restrict__ omega) {
    int e = blockIdx.x * blockDim.x + threadIdx.x;
    if (e < ECNT) {
        int h = head[e];
        float a = omega[e] / (g_seg_omega[h] + EPSV);
        g_alpha[e] = a;
        float e0 = (a > GAMMAV) ? a : 0.0f;
        g_eta0[e] = e0;
        atomicAdd(&g_seg_eta[h], e0);
    }
}

// Hierarchical warp-shuffle exclusive scan. 1024 threads, 4096 elems per
// iteration, 3 barriers per iteration. Block 0 scans the entity counts,
// block 1 scans the user counts (independent).
__global__ void k_scan2() {
    const int which = blockIdx.x;
    const int n     = which ? NUSR    : NENT;
    const int* cnt  = which ? g_cnt_u : g_cnt_e;
    int* off        = which ? g_off_u : g_off_e;
    int* cur        = which ? g_cur_u : g_cur_e;

    __shared__ int warpsum[32];
    __shared__ int carry;
    int t = threadIdx.x;
    int lane = t & 31, wid = t >> 5;
    if (t == 0) carry = 0;
    __syncthreads();

    for (int base = 0; base < n; base += 4096) {
        int v[4], loc = 0;
        #pragma unroll
        for (int k = 0; k < 4; k++) {
            int i = base + t * 4 + k;
            v[k] = (i < n) ? cnt[i] : 0;
            loc += v[k];
        }
        // warp inclusive scan of per-thread sums
        int x = loc;
        #pragma unroll
        for (int o = 1; o < 32; o <<= 1) {
            int y = __shfl_up_sync(0xffffffffu, x, o);
            if (lane >= o) x += y;
        }
        if (lane == 31) warpsum[wid] = x;
        __syncthreads();
        if (wid == 0) {
            int w = warpsum[lane];
            #pragma unroll
            for (int o = 1; o < 32; o <<= 1) {
                int y = __shfl_up_sync(0xffffffffu, w, o);
                if (lane >= o) w += y;
            }
            warpsum[lane] = w;
        }
        __syncthreads();
        int excl = carry + (wid > 0 ? warpsum[wid - 1] : 0) + (x - loc);
        #pragma unroll
        for (int k = 0; k < 4; k++) {
            int i = base + t * 4 + k;
            if (i < n) { off[i] = excl; cur[i] = excl; }
            excl += v[k];
        }
        __syncthreads();               // everyone done reading carry/warpsum
        if (t == 0) carry += warpsum[31];
        __syncthreads();               // carry update visible for next iter
    }
    if (t == 0) off[n] = carry;
}

__global__ void k_fill(const int* __restrict__ head, const int* __restrict__ tail,
                       const int* __restrict__ etype,
                       const int* __restrict__ iu, const int* __restrict__ ii,
                       const float* __restrict__ w) {
    int e = blockIdx.x * blockDim.x + threadIdx.x;
    if (e < ECNT) {
        int h = head[e];
        int pos = atomicAdd(&g_cur_e[h], 1);
        g_p_tail[pos]  = tail[e];
        g_p_rel[pos]   = etype[e] - 1;
        g_p_alpha[pos] = g_alpha[e];
        g_p_eta[pos]   = g_eta0[e] / (g_seg_eta[h] + EPSV);
    }
    if (e < IECNT) {
        int u = iu[e];
        int pos = atomicAdd(&g_cur_u[u], 1);
        g_p_item[pos] = ii[e];
        g_p_w[pos]    = w[e];
    }
}

// ---------------- fused hop kernel --------------------------------------------
// One 64-thread block per output row (entities first, then users). Each thread
// owns one float4. Gathers incoming messages, mean (entities), l2norm, clean,
// writes next-hop state (entities) and accumulates the residual into out.
// No atomics, no zeroing passes.
__global__ void k_hop(int srcSel, int dstSel, int useEta, int hop0,
                      const float4* __restrict__ in_ent,
                      const float4* __restrict__ user4,
                      const float4* __restrict__ rel4,
                      float4* __restrict__ outE,
                      float4* __restrict__ outU) {
    const float4* src = (srcSel < 0) ? in_ent : (const float4*)g_ent[srcSel];
    int c = threadIdx.x;
    int b = blockIdx.x;
    float4 acc = make_float4(0.f, 0.f, 0.f, 0.f);

    if (b < NENT) {
        int row = b;
        int beg = g_off_e[row], end = g_off_e[row + 1];
        for (int p = beg; p < end; ++p) {
            int   t   = g_p_tail[p];
            int   r   = g_p_rel[p];
            float rho = useEta ? g_p_eta[p] : g_p_alpha[p];
            float4 ev = src[(long)t * D4 + c];
            float4 rv = rel4[(long)r * D4 + c];
            acc.x = fmaf(rho * rv.x, ev.x, acc.x);
            acc.y = fmaf(rho * rv.y, ev.y, acc.y);
            acc.z = fmaf(rho * rv.z, ev.z, acc.z);
            acc.w = fmaf(rho * rv.w, ev.w, acc.w);
        }
        float inv = 1.0f / fmaxf((float)(end - beg), 1.0f);
        acc.x *= inv; acc.y *= inv; acc.z *= inv; acc.w *= inv;
        float ss = red64(acc.x * acc.x + acc.y * acc.y + acc.z * acc.z + acc.w * acc.w);
        float innorm = 1.0f / fmaxf(sqrtf(ss), EPSV);
        float4 v = make_float4(cleanv(acc.x * innorm), cleanv(acc.y * innorm),
                               cleanv(acc.z * innorm), cleanv(acc.w * innorm));
        long rb = (long)row * D4 + c;
        ((float4*)g_ent[dstSel])[rb] = v;
        float4 base = hop0 ? src[rb] : outE[rb];
        outE[rb] = make_float4(base.x + v.x, base.y + v.y, base.z + v.z, base.w + v.w);
    } else {
        int row = b - NENT;
        int beg = g_off_u[row], end = g_off_u[row + 1];
        for (int p = beg; p < end; ++p) {
            int   it = g_p_item[p];
            float w  = g_p_w[p];
            float4 ev = src[(long)it * D4 + c];
            acc.x = fmaf(w, ev.x, acc.x);
            acc.y = fmaf(w, ev.y, acc.y);
            acc.z = fmaf(w, ev.z, acc.z);
            acc.w = fmaf(w, ev.w, acc.w);
        }
        float ss = red64(acc.x * acc.x + acc.y * acc.y + acc.z * acc.z + acc.w * acc.w);
        float innorm = 1.0f / fmaxf(sqrtf(ss), EPSV);
        float4 v = make_float4(cleanv(acc.x * innorm), cleanv(acc.y * innorm),
                               cleanv(acc.z * innorm), cleanv(acc.w * innorm));
        long rb = (long)row * D4 + c;
        float4 base = hop0 ? user4[rb] : outU[rb];
        outU[rb] = make_float4(base.x + v.x, base.y + v.y, base.z + v.z, base.w + v.w);
    }
}

// ---------------- launch ------------------------------------------------------
extern "C" void kernel_launch(void* const* d_in, const int* in_sizes, int n_in,
                              void* d_out, int out_size) {
    const float* user_emb   = (const float*)d_in[0];
    const float* entity_emb = (const float*)d_in[1];
    const int*   edge_index = (const int*)d_in[2];   // [2, E]
    const int*   edge_type  = (const int*)d_in[3];
    const float* omega      = (const float*)d_in[4];
    const int*   inter_edge = (const int*)d_in[5];   // [2, IE]
    const float* inter_w    = (const float*)d_in[6];
    const float* rel_emb    = (const float*)d_in[7];
    float* out = (float*)d_out;

    const int* head = edge_index;
    const int* tail = edge_index + ECNT;
    const int* iu   = inter_edge;
    const int* ii   = inter_edge + IECNT;

    const float4* ent_in = (const float4*)entity_emb;
    const float4* usr_in = (const float4*)user_emb;
    const float4* rel4   = (const float4*)rel_emb;
    float4* outE = (float4*)out;
    float4* outU = (float4*)(out + (long)NENT * DD);

    const int T = 256;
    // CSR build + alpha/eta precompute
    k_zero <<<(NENT + T - 1) / T, T>>>();
    k_count<<<(ECNT + T - 1) / T, T>>>(head, omega, iu);
    k_alpha<<<(ECNT + T - 1) / T, T>>>(head, omega);
    k_scan2<<<2, 1024>>>();
    k_fill <<<(ECNT + T - 1) / T, T>>>(head, tail, edge_type, iu, ii, inter_w);

    const int G = NENT + NUSR;
    // hop 1: src=input, dst=buf0 ; hop 2: src=buf0, dst=buf1 ; hop 3: src=buf1, dst=buf0
    k_hop<<<G, D4>>>(-1, 0, /*useEta=*/0, /*hop0=*/1, ent_in, usr_in, rel4, outE, outU);
    k_hop<<<G, D4>>>( 0, 1, /*useEta=*/0, /*hop0=*/0, ent_in, usr_in, rel4, outE, outU);
    k_hop<<<G, D4>>>( 1, 0, /*useEta=*/1, /*hop0=*/0, ent_in, usr_in, rel4, outE, outU);
}

// round 4
// speedup vs baseline: 4.5869x; 1.0618x over previous
#include <cuda_runtime.h>
#include <math.h>

#define ECNT   300000
#define IECNT  300000
#define NENT   100000
#define NUSR   50000
#define DD     256
#define D4     64
#define EPSV   1e-8f
#define GAMMAV 0.2f

#define TILE   4096
#define EB     ((NENT + TILE - 1) / TILE)   // 25
#define UB     ((NUSR + TILE - 1) / TILE)   // 13

// ---------------- scratch (device globals; no allocations allowed) -----------
__device__ int   g_cnt_e[NENT];
__device__ int   g_cnt_u[NUSR];
__device__ int   g_off_e[NENT + 1];
__device__ int   g_off_u[NUSR + 1];
__device__ int   g_cur_e[NENT];
__device__ int   g_cur_u[NUSR];
__device__ int   g_tilesum[EB + UB];
__device__ int   g_tileoff[EB + UB];
__device__ float g_seg_omega[NENT];
__device__ float g_seg_eta[NENT];
__device__ float g_alpha[ECNT];   // per-edge alpha (edge order)
__device__ float g_eta0[ECNT];    // per-edge eta0  (edge order)
// CSR-permuted edge payloads
__device__ int   g_p_tail[ECNT];
__device__ int   g_p_rel[ECNT];   // 0-based relation id
__device__ float g_p_alpha[ECNT];
__device__ float g_p_eta[ECNT];
__device__ int   g_p_item[IECNT];
__device__ float g_p_w[IECNT];
// ping-pong entity state (input embedding serves as hop-0 source)
__device__ float g_ent[2][NENT * DD];

// ---------------- helpers ----------------------------------------------------
__device__ __forceinline__ float cleanv(float v) {
    if (isnan(v)) return 0.0f;
    if (isinf(v)) return v > 0.f ? 10000.0f : 0.0001f;
    return v;
}

// ---------------- CSR build ---------------------------------------------------
__global__ void k_zero() {
    int i = blockIdx.x * blockDim.x + threadIdx.x;
    if (i < NENT) { g_cnt_e[i] = 0; g_seg_omega[i] = 0.f; g_seg_eta[i] = 0.f; }
    if (i < NUSR) { g_cnt_u[i] = 0; }
}

__global__ void k_count(const int* __restrict__ head, const float* __restrict__ omega,
                        const int* __restrict__ iu) {
    int e = blockIdx.x * blockDim.x + threadIdx.x;
    if (e < ECNT) {
        int h = head[e];
        atomicAdd(&g_cnt_e[h], 1);
        atomicAdd(&g_seg_omega[h], omega[e]);
    }
    if (e < IECNT) {
        atomicAdd(&g_cnt_u[iu[e]], 1);
    }
}

__global__ void k_alpha(const int* __restrict__ head, const float* __restrict__ omega) {
    int e = blockIdx.x * blockDim.x + threadIdx.x;
    if (e < ECNT) {
        int h = head[e];
        float a = omega[e] / (g_seg_omega[h] + EPSV);
        g_alpha[e] = a;
        float e0 = (a > GAMMAV) ? a : 0.0f;
        g_eta0[e] = e0;
        atomicAdd(&g_seg_eta[h], e0);
    }
}

// Pass A: per-tile sums (38 independent blocks, fully parallel)
__global__ void k_scanA() {
    int b = blockIdx.x;
    int which = (b >= EB);
    int tb = which ? b - EB : b;
    const int* cnt = which ? g_cnt_u : g_cnt_e;
    int n          = which ? NUSR    : NENT;
    int base = tb * TILE + threadIdx.x * 16;
    int s = 0;
    #pragma unroll
    for (int k = 0; k < 16; k++) {
        int i = base + k;
        s += (i < n) ? cnt[i] : 0;
    }
    // block reduce (256 threads)
    __shared__ int sh[8];
    int lane = threadIdx.x & 31, wid = threadIdx.x >> 5;
    #pragma unroll
    for (int o = 16; o > 0; o >>= 1) s += __shfl_down_sync(0xffffffffu, s, o);
    if (lane == 0) sh[wid] = s;
    __syncthreads();
    if (threadIdx.x == 0) {
        int t = 0;
        #pragma unroll
        for (int i = 0; i < 8; i++) t += sh[i];
        g_tilesum[b] = t;
    }
}

// Pass B: scan the tile sums (one tiny block; warp 0 = entities, warp 1 = users)
__global__ void k_scanB() {
    int lane = threadIdx.x & 31;
    int wid  = threadIdx.x >> 5;
    int nb   = wid ? UB : EB;
    int base = wid ? EB : 0;
    int v = (lane < nb) ? g_tilesum[base + lane] : 0;
    int x = v;
    #pragma unroll
    for (int o = 1; o < 32; o <<= 1) {
        int y = __shfl_up_sync(0xffffffffu, x, o);
        if (lane >= o) x += y;
    }
    if (lane < nb) g_tileoff[base + lane] = x - v;
    if (lane == 31) {
        if (wid == 0) g_off_e[NENT] = x; else g_off_u[NUSR] = x;
    }
}

// Pass C: re-scan each tile with its global offset, write off/cur
__global__ void k_scanC() {
    int b = blockIdx.x;
    int which = (b >= EB);
    int tb = which ? b - EB : b;
    const int* cnt = which ? g_cnt_u : g_cnt_e;
    int* off       = which ? g_off_u : g_off_e;
    int* cur       = which ? g_cur_u : g_cur_e;
    int n          = which ? NUSR    : NENT;

    int t = threadIdx.x;
    int lane = t & 31, wid = t >> 5;
    int base = tb * TILE + t * 16;
    int v[16], loc = 0;
    #pragma unroll
    for (int k = 0; k < 16; k++) {
        int i = base + k;
        v[k] = (i < n) ? cnt[i] : 0;
        loc += v[k];
    }
    // warp inclusive scan of per-thread sums
    int x = loc;
    #pragma unroll
    for (int o = 1; o < 32; o <<= 1) {
        int y = __shfl_up_sync(0xffffffffu, x, o);
        if (lane >= o) x += y;
    }
    __shared__ int warpsum[8];
    if (lane == 31) warpsum[wid] = x;
    __syncthreads();
    int wpre = 0;
    #pragma unroll
    for (int i = 0; i < 8; i++) wpre += (i < wid) ? warpsum[i] : 0;
    int excl = g_tileoff[b] + wpre + (x - loc);
    #pragma unroll
    for (int k = 0; k < 16; k++) {
        int i = base + k;
        if (i < n) { off[i] = excl; cur[i] = excl; }
        excl += v[k];
    }
}

__global__ void k_fill(const int* __restrict__ head, const int* __restrict__ tail,
                       const int* __restrict__ etype,
                       const int* __restrict__ iu, const int* __restrict__ ii,
                       const float* __restrict__ w) {
    int e = blockIdx.x * blockDim.x + threadIdx.x;
    if (e < ECNT) {
        int h = head[e];
        int pos = atomicAdd(&g_cur_e[h], 1);
        g_p_tail[pos]  = tail[e];
        g_p_rel[pos]   = etype[e] - 1;
        g_p_alpha[pos] = g_alpha[e];
        g_p_eta[pos]   = g_eta0[e] / (g_seg_eta[h] + EPSV);
    }
    if (e < IECNT) {
        int u = iu[e];
        int pos = atomicAdd(&g_cur_u[u], 1);
        g_p_item[pos] = ii[e];
        g_p_w[pos]    = w[e];
    }
}

// ---------------- fused hop kernel --------------------------------------------
// One WARP per output row (entities first, then users). Each lane owns two
// float4s (columns lane and lane+32). Gathers incoming messages, mean
// (entities), l2norm via pure shfl reduce, clean, writes next-hop state
// (unless last hop) and accumulates the residual into out.
__global__ void __launch_bounds__(256) k_hop(
                      int srcSel, int dstSel, int useEta, int hop0,
                      const float4* __restrict__ in_ent,
                      const float4* __restrict__ user4,
                      const float4* __restrict__ rel4,
                      float4* __restrict__ outE,
                      float4* __restrict__ outU) {
    const float4* src = (srcSel < 0) ? in_ent : (const float4*)g_ent[srcSel];
    int gw   = (blockIdx.x * blockDim.x + threadIdx.x) >> 5;
    int lane = threadIdx.x & 31;
    if (gw >= NENT + NUSR) return;

    float4 a0 = make_float4(0.f, 0.f, 0.f, 0.f);
    float4 a1 = make_float4(0.f, 0.f, 0.f, 0.f);

    if (gw < NENT) {
        int row = gw;
        int beg = g_off_e[row], end = g_off_e[row + 1];
        const float* rho_arr = useEta ? g_p_eta : g_p_alpha;
        for (int p = beg; p < end; ++p) {
            int   t   = g_p_tail[p];
            int   r   = g_p_rel[p];
            float rho = rho_arr[p];
            const float4* sp = src  + (long)t * D4;
            const float4* rp = rel4 + (long)r * D4;
            float4 e0 = sp[lane],      e1 = sp[lane + 32];
            float4 r0 = rp[lane],      r1 = rp[lane + 32];
            a0.x = fmaf(rho * r0.x, e0.x, a0.x);
            a0.y = fmaf(rho * r0.y, e0.y, a0.y);
            a0.z = fmaf(rho * r0.z, e0.z, a0.z);
            a0.w = fmaf(rho * r0.w, e0.w, a0.w);
            a1.x = fmaf(rho * r1.x, e1.x, a1.x);
            a1.y = fmaf(rho * r1.y, e1.y, a1.y);
            a1.z = fmaf(rho * r1.z, e1.z, a1.z);
            a1.w = fmaf(rho * r1.w, e1.w, a1.w);
        }
        float inv = 1.0f / fmaxf((float)(end - beg), 1.0f);
        a0.x *= inv; a0.y *= inv; a0.z *= inv; a0.w *= inv;
        a1.x *= inv; a1.y *= inv; a1.z *= inv; a1.w *= inv;
        float ss = a0.x * a0.x + a0.y * a0.y + a0.z * a0.z + a0.w * a0.w
                 + a1.x * a1.x + a1.y * a1.y + a1.z * a1.z + a1.w * a1.w;
        #pragma unroll
        for (int o = 16; o > 0; o >>= 1) ss += __shfl_xor_sync(0xffffffffu, ss, o);
        float innorm = 1.0f / fmaxf(sqrtf(ss), EPSV);
        float4 v0 = make_float4(cleanv(a0.x * innorm), cleanv(a0.y * innorm),
                                cleanv(a0.z * innorm), cleanv(a0.w * innorm));
        float4 v1 = make_float4(cleanv(a1.x * innorm), cleanv(a1.y * innorm),
                                cleanv(a1.z * innorm), cleanv(a1.w * innorm));
        long rb = (long)row * D4;
        if (dstSel >= 0) {
            float4* dst = (float4*)g_ent[dstSel];
            dst[rb + lane]      = v0;
            dst[rb + lane + 32] = v1;
        }
        float4 b0 = hop0 ? src[rb + lane]      : outE[rb + lane];
        float4 b1 = hop0 ? src[rb + lane + 32] : outE[rb + lane + 32];
        outE[rb + lane]      = make_float4(b0.x + v0.x, b0.y + v0.y, b0.z + v0.z, b0.w + v0.w);
        outE[rb + lane + 32] = make_float4(b1.x + v1.x, b1.y + v1.y, b1.z + v1.z, b1.w + v1.w);
    } else {
        int row = gw - NENT;
        int beg = g_off_u[row], end = g_off_u[row + 1];
        for (int p = beg; p < end; ++p) {
            int   it = g_p_item[p];
            float w  = g_p_w[p];
            const float4* sp = src + (long)it * D4;
            float4 e0 = sp[lane], e1 = sp[lane + 32];
            a0.x = fmaf(w, e0.x, a0.x);
            a0.y = fmaf(w, e0.y, a0.y);
            a0.z = fmaf(w, e0.z, a0.z);
            a0.w = fmaf(w, e0.w, a0.w);
            a1.x = fmaf(w, e1.x, a1.x);
            a1.y = fmaf(w, e1.y, a1.y);
            a1.z = fmaf(w, e1.z, a1.z);
            a1.w = fmaf(w, e1.w, a1.w);
        }
        float ss = a0.x * a0.x + a0.y * a0.y + a0.z * a0.z + a0.w * a0.w
                 + a1.x * a1.x + a1.y * a1.y + a1.z * a1.z + a1.w * a1.w;
        #pragma unroll
        for (int o = 16; o > 0; o >>= 1) ss += __shfl_xor_sync(0xffffffffu, ss, o);
        float innorm = 1.0f / fmaxf(sqrtf(ss), EPSV);
        float4 v0 = make_float4(cleanv(a0.x * innorm), cleanv(a0.y * innorm),
                                cleanv(a0.z * innorm), cleanv(a0.w * innorm));
        float4 v1 = make_float4(cleanv(a1.x * innorm), cleanv(a1.y * innorm),
                                cleanv(a1.z * innorm), cleanv(a1.w * innorm));
        long rb = (long)row * D4;
        float4 b0 = hop0 ? user4[rb + lane]      : outU[rb + lane];
        float4 b1 = hop0 ? user4[rb + lane + 32] : outU[rb + lane + 32];
        outU[rb + lane]      = make_float4(b0.x + v0.x, b0.y + v0.y, b0.z + v0.z, b0.w + v0.w);
        outU[rb + lane + 32] = make_float4(b1.x + v1.x, b1.y + v1.y, b1.z + v1.z, b1.w + v1.w);
    }
}

// ---------------- launch ------------------------------------------------------
extern "C" void kernel_launch(void* const* d_in, const int* in_sizes, int n_in,
                              void* d_out, int out_size) {
    const float* user_emb   = (const float*)d_in[0];
    const float* entity_emb = (const float*)d_in[1];
    const int*   edge_index = (const int*)d_in[2];   // [2, E]
    const int*   edge_type  = (const int*)d_in[3];
    const float* omega      = (const float*)d_in[4];
    const int*   inter_edge = (const int*)d_in[5];   // [2, IE]
    const float* inter_w    = (const float*)d_in[6];
    const float* rel_emb    = (const float*)d_in[7];
    float* out = (float*)d_out;

    const int* head = edge_index;
    const int* tail = edge_index + ECNT;
    const int* iu   = inter_edge;
    const int* ii   = inter_edge + IECNT;

    const float4* ent_in = (const float4*)entity_emb;
    const float4* usr_in = (const float4*)user_emb;
    const float4* rel4   = (const float4*)rel_emb;
    float4* outE = (float4*)out;
    float4* outU = (float4*)(out + (long)NENT * DD);

    const int T = 256;
    // CSR build + alpha/eta precompute
    k_zero <<<(NENT + T - 1) / T, T>>>();
    k_count<<<(ECNT + T - 1) / T, T>>>(head, omega, iu);
    k_alpha<<<(ECNT + T - 1) / T, T>>>(head, omega);
    k_scanA<<<EB + UB, T>>>();
    k_scanB<<<1, 64>>>();
    k_scanC<<<EB + UB, T>>>();
    k_fill <<<(ECNT + T - 1) / T, T>>>(head, tail, edge_type, iu, ii, inter_w);

    const int G = ((NENT + NUSR) * 32 + T - 1) / T;   // one warp per row
    // hop 1: src=input, dst=buf0 ; hop 2: src=buf0, dst=buf1 ; hop 3: src=buf1 (no state write)
    k_hop<<<G, T>>>(-1,  0, /*useEta=*/0, /*hop0=*/1, ent_in, usr_in, rel4, outE, outU);
    k_hop<<<G, T>>>( 0,  1, /*useEta=*/0, /*hop0=*/0, ent_in, usr_in, rel4, outE, outU);
    k_hop<<<G, T>>>( 1, -1, /*useEta=*/1, /*hop0=*/0, ent_in, usr_in, rel4, outE, outU);
}

// round 5
// speedup vs baseline: 6.8207x; 1.4870x over previous
#include <cuda_runtime.h>
#include <cuda_fp16.h>
#include <math.h>

#define ECNT   300000
#define IECNT  300000
#define NENT   100000
#define NUSR   50000
#define DD     256
#define D4     64
#define EPSV   1e-8f
#define GAMMAV 0.2f

#define TILE   4096
#define EB     ((NENT + TILE - 1) / TILE)   // 25
#define UB     ((NUSR + TILE - 1) / TILE)   // 13

struct EdgeE { int tail; int rel; float alpha; float eta; };   // 16B
struct EdgeU { int item; float w; };                           // 8B

// ---------------- scratch (device globals; no allocations allowed) -----------
__device__ int    g_cnt_e[NENT];       // zero at module load; restored by k_cleanup
__device__ int    g_cnt_u[NUSR];
__device__ float  g_seg_omega[NENT];
__device__ float  g_seg_eta[NENT];
__device__ int    g_off_e[NENT + 1];
__device__ int    g_off_u[NUSR + 1];
__device__ int    g_cur_e[NENT];
__device__ int    g_cur_u[NUSR];
__device__ int    g_tilesum[EB + UB];
__device__ float  g_alpha[ECNT];
__device__ float  g_eta0[ECNT];
__device__ EdgeE  g_pe[ECNT];
__device__ EdgeU  g_pu[IECNT];
// fp16 entity states: [0],[1] = ping-pong hop states, [2] = fp16 copy of input
__device__ __half g_enth[3][NENT * DD];

// ---------------- helpers ----------------------------------------------------
__device__ __forceinline__ float cleanv(float v) {
    if (isnan(v)) return 0.0f;
    if (isinf(v)) return v > 0.f ? 10000.0f : 0.0001f;
    return v;
}

// ---------------- precompute --------------------------------------------------
__global__ void k_count(const int* __restrict__ head, const float* __restrict__ omega,
                        const int* __restrict__ iu) {
    int e = blockIdx.x * blockDim.x + threadIdx.x;
    if (e < ECNT) {
        int h = head[e];
        atomicAdd(&g_cnt_e[h], 1);
        atomicAdd(&g_seg_omega[h], omega[e]);
    }
    if (e < IECNT) {
        atomicAdd(&g_cnt_u[iu[e]], 1);
    }
}

__global__ void k_alpha(const int* __restrict__ head, const float* __restrict__ omega) {
    int e = blockIdx.x * blockDim.x + threadIdx.x;
    if (e < ECNT) {
        int h = head[e];
        float a = omega[e] / (g_seg_omega[h] + EPSV);
        g_alpha[e] = a;
        float e0 = (a > GAMMAV) ? a : 0.0f;
        g_eta0[e] = e0;
        atomicAdd(&g_seg_eta[h], e0);
    }
}

// Pass A: per-tile sums (38 independent blocks)
__global__ void k_scanA() {
    int b = blockIdx.x;
    int which = (b >= EB);
    int tb = which ? b - EB : b;
    const int* cnt = which ? g_cnt_u : g_cnt_e;
    int n          = which ? NUSR    : NENT;
    int base = tb * TILE + threadIdx.x * 16;
    int s = 0;
    #pragma unroll
    for (int k = 0; k < 16; k++) {
        int i = base + k;
        s += (i < n) ? cnt[i] : 0;
    }
    __shared__ int sh[8];
    int lane = threadIdx.x & 31, wid = threadIdx.x >> 5;
    #pragma unroll
    for (int o = 16; o > 0; o >>= 1) s += __shfl_down_sync(0xffffffffu, s, o);
    if (lane == 0) sh[wid] = s;
    __syncthreads();
    if (threadIdx.x == 0) {
        int t = 0;
        #pragma unroll
        for (int i = 0; i < 8; i++) t += sh[i];
        g_tilesum[b] = t;
    }
}

// Pass B+C merged: each block redundantly scans the (<=25) tile sums of its
// segment, then re-scans its own tile with the global offset.
__global__ void k_scanBC() {
    int b = blockIdx.x;
    int which = (b >= EB);
    int tb = which ? b - EB : b;
    const int* cnt = which ? g_cnt_u : g_cnt_e;
    int* off       = which ? g_off_u : g_off_e;
    int* cur       = which ? g_cur_u : g_cur_e;
    int n          = which ? NUSR    : NENT;
    int nb         = which ? UB      : EB;
    int sbase      = which ? EB      : 0;

    __shared__ int s_tileoff;
    if (threadIdx.x < 32) {
        int lane = threadIdx.x;
        int v = (lane < nb) ? g_tilesum[sbase + lane] : 0;
        int x = v;
        #pragma unroll
        for (int o = 1; o < 32; o <<= 1) {
            int y = __shfl_up_sync(0xffffffffu, x, o);
            if (lane >= o) x += y;
        }
        if (lane == tb) s_tileoff = x - v;
    }
    __syncthreads();

    int t = threadIdx.x;
    int lane = t & 31, wid = t >> 5;
    int base = tb * TILE + t * 16;
    int v[16], loc = 0;
    #pragma unroll
    for (int k = 0; k < 16; k++) {
        int i = base + k;
        v[k] = (i < n) ? cnt[i] : 0;
        loc += v[k];
    }
    int x = loc;
    #pragma unroll
    for (int o = 1; o < 32; o <<= 1) {
        int y = __shfl_up_sync(0xffffffffu, x, o);
        if (lane >= o) x += y;
    }
    __shared__ int warpsum[8];
    if (lane == 31) warpsum[wid] = x;
    __syncthreads();
    int wpre = 0;
    #pragma unroll
    for (int i = 0; i < 8; i++) wpre += (i < wid) ? warpsum[i] : 0;
    int excl = s_tileoff + wpre + (x - loc);
    #pragma unroll
    for (int k = 0; k < 16; k++) {
        int i = base + k;
        if (i < n) { off[i] = excl; cur[i] = excl; }
        else if (i == n) { off[n] = excl; }
        excl += v[k];
    }
}

// CSR fill (packed payloads) + fp16 conversion of the input entity embedding.
__global__ void k_fillconv(const int* __restrict__ head, const int* __restrict__ tail,
                           const int* __restrict__ etype,
                           const int* __restrict__ iu, const int* __restrict__ ii,
                           const float* __restrict__ w,
                           const float2* __restrict__ ent_in2) {
    int e = blockIdx.x * blockDim.x + threadIdx.x;
    if (e < ECNT) {
        int h = head[e];
        int pos = atomicAdd(&g_cur_e[h], 1);
        EdgeE ed;
        ed.tail  = tail[e];
        ed.rel   = etype[e] - 1;
        ed.alpha = g_alpha[e];
        ed.eta   = g_eta0[e] / (g_seg_eta[h] + EPSV);
        g_pe[pos] = ed;
    }
    if (e < IECNT) {
        int u = iu[e];
        int pos = atomicAdd(&g_cur_u[u], 1);
        EdgeU eu;
        eu.item = ii[e];
        eu.w    = w[e];
        g_pu[pos] = eu;
    }
    // fp16 copy of the input entity embedding (grid-stride)
    __half2* dst = (__half2*)g_enth[2];
    long total = (long)gridDim.x * blockDim.x;
    const long NH2 = (long)NENT * DD / 2;
    for (long i = e; i < NH2; i += total) {
        dst[i] = __float22half2_rn(ent_in2[i]);
    }
}

// restore the zero-invariant for the next replay (device globals start zeroed)
__global__ void k_cleanup() {
    int i = blockIdx.x * blockDim.x + threadIdx.x;
    if (i < NENT) { g_cnt_e[i] = 0; g_seg_omega[i] = 0.f; g_seg_eta[i] = 0.f; }
    if (i < NUSR) { g_cnt_u[i] = 0; }
}

// ---------------- fused hop kernel --------------------------------------------
// One WARP per output row (entities first, then users). Each lane owns 8
// consecutive channels: gathers are one 16B (8 x fp16) load per lane per edge.
// Accumulation / norm / residual all fp32.
__global__ void __launch_bounds__(256) k_hop(
                      int srcSel, int dstSel, int useEta, int hop0,
                      const float4* __restrict__ ent_in,
                      const float4* __restrict__ user4,
                      const float4* __restrict__ rel4,
                      float4* __restrict__ outE,
                      float4* __restrict__ outU) {
    const __half* srcH = g_enth[srcSel];
    int gw   = (blockIdx.x * blockDim.x + threadIdx.x) >> 5;
    int lane = threadIdx.x & 31;
    if (gw >= NENT + NUSR) return;

    float acc[8];
    #pragma unroll
    for (int k = 0; k < 8; k++) acc[k] = 0.f;

    if (gw < NENT) {
        int row = gw;
        int beg = g_off_e[row], end = g_off_e[row + 1];
        for (int p = beg; p < end; ++p) {
            EdgeE ed = g_pe[p];
            float rho = useEta ? ed.eta : ed.alpha;
            uint4 hv = ((const uint4*)(srcH + (long)ed.tail * DD))[lane];
            const __half2* hp = (const __half2*)&hv;
            const float4* rp = rel4 + (long)ed.rel * D4 + lane * 2;
            float4 r0 = rp[0], r1 = rp[1];
            float2 f0 = __half22float2(hp[0]);
            float2 f1 = __half22float2(hp[1]);
            float2 f2 = __half22float2(hp[2]);
            float2 f3 = __half22float2(hp[3]);
            acc[0] = fmaf(rho * r0.x, f0.x, acc[0]);
            acc[1] = fmaf(rho * r0.y, f0.y, acc[1]);
            acc[2] = fmaf(rho * r0.z, f1.x, acc[2]);
            acc[3] = fmaf(rho * r0.w, f1.y, acc[3]);
            acc[4] = fmaf(rho * r1.x, f2.x, acc[4]);
            acc[5] = fmaf(rho * r1.y, f2.y, acc[5]);
            acc[6] = fmaf(rho * r1.z, f3.x, acc[6]);
            acc[7] = fmaf(rho * r1.w, f3.y, acc[7]);
        }
        float inv = 1.0f / fmaxf((float)(end - beg), 1.0f);
        float ss = 0.f;
        #pragma unroll
        for (int k = 0; k < 8; k++) { acc[k] *= inv; ss = fmaf(acc[k], acc[k], ss); }
        #pragma unroll
        for (int o = 16; o > 0; o >>= 1) ss += __shfl_xor_sync(0xffffffffu, ss, o);
        float innorm = 1.0f / fmaxf(sqrtf(ss), EPSV);
        float v[8];
        #pragma unroll
        for (int k = 0; k < 8; k++) v[k] = cleanv(acc[k] * innorm);

        if (dstSel >= 0) {
            uint4 hv;
            __half2* hp = (__half2*)&hv;
            hp[0] = __floats2half2_rn(v[0], v[1]);
            hp[1] = __floats2half2_rn(v[2], v[3]);
            hp[2] = __floats2half2_rn(v[4], v[5]);
            hp[3] = __floats2half2_rn(v[6], v[7]);
            ((uint4*)(g_enth[dstSel] + (long)row * DD))[lane] = hv;
        }
        long o0 = (long)row * D4 + lane * 2;
        float4 b0 = hop0 ? ent_in[o0]     : outE[o0];
        float4 b1 = hop0 ? ent_in[o0 + 1] : outE[o0 + 1];
        outE[o0]     = make_float4(b0.x + v[0], b0.y + v[1], b0.z + v[2], b0.w + v[3]);
        outE[o0 + 1] = make_float4(b1.x + v[4], b1.y + v[5], b1.z + v[6], b1.w + v[7]);
    } else {
        int row = gw - NENT;
        int beg = g_off_u[row], end = g_off_u[row + 1];
        for (int p = beg; p < end; ++p) {
            EdgeU eu = g_pu[p];
            float w = eu.w;
            uint4 hv = ((const uint4*)(srcH + (long)eu.item * DD))[lane];
            const __half2* hp = (const __half2*)&hv;
            float2 f0 = __half22float2(hp[0]);
            float2 f1 = __half22float2(hp[1]);
            float2 f2 = __half22float2(hp[2]);
            float2 f3 = __half22float2(hp[3]);
            acc[0] = fmaf(w, f0.x, acc[0]);
            acc[1] = fmaf(w, f0.y, acc[1]);
            acc[2] = fmaf(w, f1.x, acc[2]);
            acc[3] = fmaf(w, f1.y, acc[3]);
            acc[4] = fmaf(w, f2.x, acc[4]);
            acc[5] = fmaf(w, f2.y, acc[5]);
            acc[6] = fmaf(w, f3.x, acc[6]);
            acc[7] = fmaf(w, f3.y, acc[7]);
        }
        float ss = 0.f;
        #pragma unroll
        for (int k = 0; k < 8; k++) ss = fmaf(acc[k], acc[k], ss);
        #pragma unroll
        for (int o = 16; o > 0; o >>= 1) ss += __shfl_xor_sync(0xffffffffu, ss, o);
        float innorm = 1.0f / fmaxf(sqrtf(ss), EPSV);
        float v[8];
        #pragma unroll
        for (int k = 0; k < 8; k++) v[k] = cleanv(acc[k] * innorm);

        long o0 = (long)row * D4 + lane * 2;
        float4 b0 = hop0 ? user4[o0]     : outU[o0];
        float4 b1 = hop0 ? user4[o0 + 1] : outU[o0 + 1];
        outU[o0]     = make_float4(b0.x + v[0], b0.y + v[1], b0.z + v[2], b0.w + v[3]);
        outU[o0 + 1] = make_float4(b1.x + v[4], b1.y + v[5], b1.z + v[6], b1.w + v[7]);
    }
}

// ---------------- launch ------------------------------------------------------
extern "C" void kernel_launch(void* const* d_in, const int* in_sizes, int n_in,
                              void* d_out, int out_size) {
    const float* user_emb   = (const float*)d_in[0];
    const float* entity_emb = (const float*)d_in[1];
    const int*   edge_index = (const int*)d_in[2];   // [2, E]
    const int*   edge_type  = (const int*)d_in[3];
    const float* omega      = (const float*)d_in[4];
    const int*   inter_edge = (const int*)d_in[5];   // [2, IE]
    const float* inter_w    = (const float*)d_in[6];
    const float* rel_emb    = (const float*)d_in[7];
    float* out = (float*)d_out;

    const int* head = edge_index;
    const int* tail = edge_index + ECNT;
    const int* iu   = inter_edge;
    const int* ii   = inter_edge + IECNT;

    const float4* ent_in = (const float4*)entity_emb;
    const float4* usr_in = (const float4*)user_emb;
    const float4* rel4   = (const float4*)rel_emb;
    float4* outE = (float4*)out;
    float4* outU = (float4*)(out + (long)NENT * DD);

    const int T = 256;
    const int EG = (ECNT + T - 1) / T;
    // counts/seg arrays are zero at entry (module load, or k_cleanup from the
    // previous call) — no zero pass needed.
    k_count   <<<EG, T>>>(head, omega, iu);                           // 0
    k_alpha   <<<EG, T>>>(head, omega);                               // 1
    k_scanA   <<<EB + UB, T>>>();                                     // 2
    k_scanBC  <<<EB + UB, T>>>();                                     // 3
    k_fillconv<<<EG, T>>>(head, tail, edge_type, iu, ii, inter_w,
                          (const float2*)entity_emb);                 // 4

    const int G = ((NENT + NUSR) * 32 + T - 1) / T;   // one warp per row
    // hop 1: src=fp16 input copy (2), dst=0 ; hop 2: 0->1 ; hop 3: 1-> (no state write)
    k_hop<<<G, T>>>(2,  0, /*useEta=*/0, /*hop0=*/1, ent_in, usr_in, rel4, outE, outU);  // 5 (profiled)
    k_hop<<<G, T>>>(0,  1, /*useEta=*/0, /*hop0=*/0, ent_in, usr_in, rel4, outE, outU);
    k_hop<<<G, T>>>(1, -1, /*useEta=*/1, /*hop0=*/0, ent_in, usr_in, rel4, outE, outU);

    k_cleanup<<<(NENT + T - 1) / T, T>>>();
}